// round 9
// baseline (speedup 1.0000x reference)
#include <cuda_runtime.h>
#include <math.h>

// ContLoss: T=512, B=64, E=1024, N=128
#define TT     512
#define BZ     64
#define EE     1024
#define NNEG   128
#define NHALF  64
#define EPSV   1e-8f
#define INV_TEMP 10.0f   // 1/TEMP, TEMP=0.1

// scratch (zero-initialized __device__ globals)
// per-CTA partial per-feature sums: [blk][ s:0..255 | q:256..511 ] float4
__device__ float4       g_psq[2 * TT * 512];   // 8 MB
__device__ unsigned int g_cnt[TT];             // per-t pair counters
__device__ float        g_partial[TT];         // per-t losses
__device__ unsigned int g_cnt2;                // global finish counter

// asm-forced vector load: ptxas cannot reorder/sink these, so batches of 8
// are truly back-to-back in SASS (real MLP=8).
__device__ __forceinline__ float4 ldg128(const float4* p) {
    float4 v;
    asm volatile("ld.global.nc.v4.f32 {%0,%1,%2,%3}, [%4];"
                 : "=f"(v.x), "=f"(v.y), "=f"(v.z), "=f"(v.w)
                 : "l"(p));
    return v;
}

// Two CTAs per t (64 negatives each), 256 threads, asm MLP=8.
// Pair-last CTA combines sibling's per-feature partials and finishes the math.
__global__ __launch_bounds__(256) void contloss_split(
    const int*   __restrict__ index,
    const float* __restrict__ z1,
    const float* __restrict__ z2,
    const int*   __restrict__ neg_s,
    const int*   __restrict__ neg_w,
    float*       __restrict__ out)
{
    const int blk = blockIdx.x;
    const int t   = blk >> 1;
    const int g   = blk & 1;
    const int tid = threadIdx.x;

    __shared__ int sh_off[NHALF];
    if (tid < NHALF) {
        const int j = t * NNEG + g * NHALF + tid;
        sh_off[tid] = (neg_s[j] * BZ + neg_w[j]) * (EE / 4);
    }
    __syncthreads();

    const float4* __restrict__ z1v = (const float4*)z1;

    float s0 = 0.f, s1 = 0.f, s2 = 0.f, s3 = 0.f;
    float q0 = 0.f, q1 = 0.f, q2 = 0.f, q3 = 0.f;

    for (int n = 0; n < NHALF; n += 8) {
        const float4 v0 = ldg128(z1v + sh_off[n + 0] + tid);
        const float4 v1 = ldg128(z1v + sh_off[n + 1] + tid);
        const float4 v2 = ldg128(z1v + sh_off[n + 2] + tid);
        const float4 v3 = ldg128(z1v + sh_off[n + 3] + tid);
        const float4 v4 = ldg128(z1v + sh_off[n + 4] + tid);
        const float4 v5 = ldg128(z1v + sh_off[n + 5] + tid);
        const float4 v6 = ldg128(z1v + sh_off[n + 6] + tid);
        const float4 v7 = ldg128(z1v + sh_off[n + 7] + tid);

        s0 += v0.x; s1 += v0.y; s2 += v0.z; s3 += v0.w;
        q0 = fmaf(v0.x, v0.x, q0); q1 = fmaf(v0.y, v0.y, q1);
        q2 = fmaf(v0.z, v0.z, q2); q3 = fmaf(v0.w, v0.w, q3);

        s0 += v1.x; s1 += v1.y; s2 += v1.z; s3 += v1.w;
        q0 = fmaf(v1.x, v1.x, q0); q1 = fmaf(v1.y, v1.y, q1);
        q2 = fmaf(v1.z, v1.z, q2); q3 = fmaf(v1.w, v1.w, q3);

        s0 += v2.x; s1 += v2.y; s2 += v2.z; s3 += v2.w;
        q0 = fmaf(v2.x, v2.x, q0); q1 = fmaf(v2.y, v2.y, q1);
        q2 = fmaf(v2.z, v2.z, q2); q3 = fmaf(v2.w, v2.w, q3);

        s0 += v3.x; s1 += v3.y; s2 += v3.z; s3 += v3.w;
        q0 = fmaf(v3.x, v3.x, q0); q1 = fmaf(v3.y, v3.y, q1);
        q2 = fmaf(v3.z, v3.z, q2); q3 = fmaf(v3.w, v3.w, q3);

        s0 += v4.x; s1 += v4.y; s2 += v4.z; s3 += v4.w;
        q0 = fmaf(v4.x, v4.x, q0); q1 = fmaf(v4.y, v4.y, q1);
        q2 = fmaf(v4.z, v4.z, q2); q3 = fmaf(v4.w, v4.w, q3);

        s0 += v5.x; s1 += v5.y; s2 += v5.z; s3 += v5.w;
        q0 = fmaf(v5.x, v5.x, q0); q1 = fmaf(v5.y, v5.y, q1);
        q2 = fmaf(v5.z, v5.z, q2); q3 = fmaf(v5.w, v5.w, q3);

        s0 += v6.x; s1 += v6.y; s2 += v6.z; s3 += v6.w;
        q0 = fmaf(v6.x, v6.x, q0); q1 = fmaf(v6.y, v6.y, q1);
        q2 = fmaf(v6.z, v6.z, q2); q3 = fmaf(v6.w, v6.w, q3);

        s0 += v7.x; s1 += v7.y; s2 += v7.z; s3 += v7.w;
        q0 = fmaf(v7.x, v7.x, q0); q1 = fmaf(v7.y, v7.y, q1);
        q2 = fmaf(v7.z, v7.z, q2); q3 = fmaf(v7.w, v7.w, q3);
    }

    // publish partials (4 KB per CTA, coalesced)
    g_psq[blk * 512 + tid]       = make_float4(s0, s1, s2, s3);
    g_psq[blk * 512 + 256 + tid] = make_float4(q0, q1, q2, q3);
    __threadfence();

    __shared__ unsigned int sh_rank;
    if (tid == 0) sh_rank = atomicAdd(&g_cnt[t], 1u);
    __syncthreads();
    if (sh_rank == 0) return;   // first of the pair exits, frees the SM slot

    // pair-last CTA: combine sibling's partials
    const int other = blk ^ 1;
    const float4 so = g_psq[other * 512 + tid];
    const float4 qo = g_psq[other * 512 + 256 + tid];
    s0 += so.x; s1 += so.y; s2 += so.z; s3 += so.w;
    q0 += qo.x; q1 += qo.y; q2 += qo.z; q3 += qo.w;

    // anchor (orig) and positive (adv) rows
    const int bidx  = __ldg(index + t);
    const int arow4 = (t * BZ + bidx) * (EE / 4);
    const float4 vo = __ldg(z1v + arow4 + tid);
    const float4 va = __ldg((const float4*)z2 + arow4 + tid);

    const float sqrtN = sqrtf((float)NNEG);

    float den = 0.f;
    {
        float o, sm, qq;
        o = vo.x; sm = s0; qq = q0;
        den += expf((o * sm) / (fmaxf(sqrtf(qq), EPSV) * fmaxf(sqrtN * fabsf(o), EPSV)) * INV_TEMP);
        o = vo.y; sm = s1; qq = q1;
        den += expf((o * sm) / (fmaxf(sqrtf(qq), EPSV) * fmaxf(sqrtN * fabsf(o), EPSV)) * INV_TEMP);
        o = vo.z; sm = s2; qq = q2;
        den += expf((o * sm) / (fmaxf(sqrtf(qq), EPSV) * fmaxf(sqrtN * fabsf(o), EPSV)) * INV_TEMP);
        o = vo.w; sm = s3; qq = q3;
        den += expf((o * sm) / (fmaxf(sqrtf(qq), EPSV) * fmaxf(sqrtN * fabsf(o), EPSV)) * INV_TEMP);
    }
    float dotp = vo.x * va.x + vo.y * va.y + vo.z * va.z + vo.w * va.w;
    float na2  = vo.x * vo.x + vo.y * vo.y + vo.z * vo.z + vo.w * vo.w;
    float nb2  = va.x * va.x + va.y * va.y + va.z * va.z + va.w * va.w;

    // deterministic block reduction
    const int lane = tid & 31;
    const int warp = tid >> 5;
    #pragma unroll
    for (int off = 16; off > 0; off >>= 1) {
        den  += __shfl_down_sync(0xffffffffu, den,  off);
        dotp += __shfl_down_sync(0xffffffffu, dotp, off);
        na2  += __shfl_down_sync(0xffffffffu, na2,  off);
        nb2  += __shfl_down_sync(0xffffffffu, nb2,  off);
    }
    __shared__ float r_den[8], r_dot[8], r_na[8], r_nb[8];
    __shared__ bool  sh_last;
    if (lane == 0) {
        r_den[warp] = den; r_dot[warp] = dotp; r_na[warp] = na2; r_nb[warp] = nb2;
    }
    __syncthreads();
    if (tid == 0) {
        float D = 0.f, P = 0.f, A = 0.f, Bv = 0.f;
        #pragma unroll
        for (int w = 0; w < 8; ++w) { D += r_den[w]; P += r_dot[w]; A += r_na[w]; Bv += r_nb[w]; }
        const float pos_cos = P / (fmaxf(sqrtf(A), EPSV) * fmaxf(sqrtf(Bv), EPSV));
        g_partial[t] = logf(D) - pos_cos * INV_TEMP;
        g_cnt[t] = 0u;            // reset pair counter for next graph replay
        __threadfence();
        const unsigned int done = atomicAdd(&g_cnt2, 1u);
        sh_last = (done == (unsigned int)(TT - 1));
    }
    __syncthreads();

    // global-last CTA: deterministic tree over the 512 per-t losses
    if (sh_last) {
        __shared__ float sh[256];
        sh[tid] = g_partial[tid] + g_partial[tid + 256];
        __syncthreads();
        #pragma unroll
        for (int s = 128; s > 0; s >>= 1) {
            if (tid < s) sh[tid] += sh[tid + s];
            __syncthreads();
        }
        if (tid == 0) {
            out[0] = sh[0];
            g_cnt2 = 0u;          // reset for next graph replay
        }
    }
}

extern "C" void kernel_launch(void* const* d_in, const int* in_sizes, int n_in,
                              void* d_out, int out_size)
{
    const int*   index = (const int*)  d_in[0];
    const float* z1    = (const float*)d_in[1];
    const float* z2    = (const float*)d_in[2];
    const int*   ns    = (const int*)  d_in[3];
    const int*   nw    = (const int*)  d_in[4];

    contloss_split<<<2 * TT, 256>>>(index, z1, z2, ns, nw, (float*)d_out);
}

// round 10
// speedup vs baseline: 1.1116x; 1.1116x over previous
#include <cuda_runtime.h>
#include <math.h>

// ContLoss: T=512, B=64, E=1024, N=128
#define TT     512
#define BZ     64
#define EE     1024
#define NNEG   128
#define EPSV   1e-8f
#define INV_TEMP 10.0f   // 1/TEMP, TEMP=0.1

// scratch (zero-initialized __device__ globals)
__device__ float        g_partial[TT];
__device__ unsigned int g_count;

// asm-forced vector load: ordering between asm volatile is preserved, so a
// batch of these is truly back-to-back in SASS (ptxas cannot sink them).
__device__ __forceinline__ float4 ldg128(const float4* p) {
    float4 v;
    asm volatile("ld.global.nc.v4.f32 {%0,%1,%2,%3}, [%4];"
                 : "=f"(v.x), "=f"(v.y), "=f"(v.z), "=f"(v.w)
                 : "l"(p));
    return v;
}

#define ACC(v)                                          \
    s0 += (v).x; s1 += (v).y; s2 += (v).z; s3 += (v).w; \
    q0 = fmaf((v).x, (v).x, q0); q1 = fmaf((v).y, (v).y, q1); \
    q2 = fmaf((v).z, (v).z, q2); q3 = fmaf((v).w, (v).w, q3)

// One CTA per t. 256 threads; thread tid owns float4 column tid.
// Hot loop: 16 asm-batched LDG.128 in flight per thread (true MLP=16).
__global__ __launch_bounds__(256, 3) void contloss_fused(
    const int*   __restrict__ index,
    const float* __restrict__ z1,
    const float* __restrict__ z2,
    const int*   __restrict__ neg_s,
    const int*   __restrict__ neg_w,
    float*       __restrict__ out)
{
    const int t   = blockIdx.x;
    const int tid = threadIdx.x;

    __shared__ int sh_off[NNEG];
    if (tid < NNEG) {
        const int j = t * NNEG + tid;
        sh_off[tid] = (neg_s[j] * BZ + neg_w[j]) * (EE / 4);
    }
    __syncthreads();

    const float4* __restrict__ z1v = (const float4*)z1;

    float s0 = 0.f, s1 = 0.f, s2 = 0.f, s3 = 0.f;
    float q0 = 0.f, q1 = 0.f, q2 = 0.f, q3 = 0.f;

    for (int n = 0; n < NNEG; n += 16) {
        // 16 guaranteed back-to-back LDG.128
        const float4 v0  = ldg128(z1v + sh_off[n +  0] + tid);
        const float4 v1  = ldg128(z1v + sh_off[n +  1] + tid);
        const float4 v2  = ldg128(z1v + sh_off[n +  2] + tid);
        const float4 v3  = ldg128(z1v + sh_off[n +  3] + tid);
        const float4 v4  = ldg128(z1v + sh_off[n +  4] + tid);
        const float4 v5  = ldg128(z1v + sh_off[n +  5] + tid);
        const float4 v6  = ldg128(z1v + sh_off[n +  6] + tid);
        const float4 v7  = ldg128(z1v + sh_off[n +  7] + tid);
        const float4 v8  = ldg128(z1v + sh_off[n +  8] + tid);
        const float4 v9  = ldg128(z1v + sh_off[n +  9] + tid);
        const float4 v10 = ldg128(z1v + sh_off[n + 10] + tid);
        const float4 v11 = ldg128(z1v + sh_off[n + 11] + tid);
        const float4 v12 = ldg128(z1v + sh_off[n + 12] + tid);
        const float4 v13 = ldg128(z1v + sh_off[n + 13] + tid);
        const float4 v14 = ldg128(z1v + sh_off[n + 14] + tid);
        const float4 v15 = ldg128(z1v + sh_off[n + 15] + tid);

        ACC(v0);  ACC(v1);  ACC(v2);  ACC(v3);
        ACC(v4);  ACC(v5);  ACC(v6);  ACC(v7);
        ACC(v8);  ACC(v9);  ACC(v10); ACC(v11);
        ACC(v12); ACC(v13); ACC(v14); ACC(v15);
    }

    // anchor (orig) and positive (adv) rows
    const int bidx  = __ldg(index + t);
    const int arow4 = (t * BZ + bidx) * (EE / 4);
    const float4 vo = __ldg(z1v + arow4 + tid);
    const float4 va = __ldg((const float4*)z2 + arow4 + tid);

    const float sqrtN = sqrtf((float)NNEG);

    float den = 0.f;
    {
        float o, sm, qq;
        o = vo.x; sm = s0; qq = q0;
        den += expf((o * sm) / (fmaxf(sqrtf(qq), EPSV) * fmaxf(sqrtN * fabsf(o), EPSV)) * INV_TEMP);
        o = vo.y; sm = s1; qq = q1;
        den += expf((o * sm) / (fmaxf(sqrtf(qq), EPSV) * fmaxf(sqrtN * fabsf(o), EPSV)) * INV_TEMP);
        o = vo.z; sm = s2; qq = q2;
        den += expf((o * sm) / (fmaxf(sqrtf(qq), EPSV) * fmaxf(sqrtN * fabsf(o), EPSV)) * INV_TEMP);
        o = vo.w; sm = s3; qq = q3;
        den += expf((o * sm) / (fmaxf(sqrtf(qq), EPSV) * fmaxf(sqrtN * fabsf(o), EPSV)) * INV_TEMP);
    }
    float dotp = vo.x * va.x + vo.y * va.y + vo.z * va.z + vo.w * va.w;
    float na2  = vo.x * vo.x + vo.y * vo.y + vo.z * vo.z + vo.w * vo.w;
    float nb2  = va.x * va.x + va.y * va.y + va.z * va.z + va.w * va.w;

    // deterministic block reduction
    const int lane = tid & 31;
    const int warp = tid >> 5;
    #pragma unroll
    for (int off = 16; off > 0; off >>= 1) {
        den  += __shfl_down_sync(0xffffffffu, den,  off);
        dotp += __shfl_down_sync(0xffffffffu, dotp, off);
        na2  += __shfl_down_sync(0xffffffffu, na2,  off);
        nb2  += __shfl_down_sync(0xffffffffu, nb2,  off);
    }
    __shared__ float r_den[8], r_dot[8], r_na[8], r_nb[8];
    __shared__ bool  sh_last;
    if (lane == 0) {
        r_den[warp] = den; r_dot[warp] = dotp; r_na[warp] = na2; r_nb[warp] = nb2;
    }
    __syncthreads();
    if (tid == 0) {
        float D = 0.f, P = 0.f, A = 0.f, Bv = 0.f;
        #pragma unroll
        for (int w = 0; w < 8; ++w) { D += r_den[w]; P += r_dot[w]; A += r_na[w]; Bv += r_nb[w]; }
        const float pos_cos = P / (fmaxf(sqrtf(A), EPSV) * fmaxf(sqrtf(Bv), EPSV));
        g_partial[t] = logf(D) - pos_cos * INV_TEMP;
        __threadfence();
        const unsigned int done = atomicAdd(&g_count, 1u);
        sh_last = (done == (unsigned int)(gridDim.x - 1));
    }
    __syncthreads();

    // global-last CTA: deterministic tree over the 512 per-t losses
    if (sh_last) {
        __shared__ float sh[256];
        sh[tid] = g_partial[tid] + g_partial[tid + 256];
        __syncthreads();
        #pragma unroll
        for (int s = 128; s > 0; s >>= 1) {
            if (tid < s) sh[tid] += sh[tid + s];
            __syncthreads();
        }
        if (tid == 0) {
            out[0]  = sh[0];
            g_count = 0u;   // reset for next graph replay
        }
    }
}

extern "C" void kernel_launch(void* const* d_in, const int* in_sizes, int n_in,
                              void* d_out, int out_size)
{
    const int*   index = (const int*)  d_in[0];
    const float* z1    = (const float*)d_in[1];
    const float* z2    = (const float*)d_in[2];
    const int*   ns    = (const int*)  d_in[3];
    const int*   nw    = (const int*)  d_in[4];

    contloss_fused<<<TT, 256>>>(index, z1, z2, ns, nw, (float*)d_out);
}

// round 11
// speedup vs baseline: 1.2905x; 1.1609x over previous
#include <cuda_runtime.h>
#include <math.h>

// ContLoss: T=512, B=64, E=1024, N=128
#define TT     512
#define BZ     64
#define EE     1024
#define NNEG   128
#define EPSV   1e-8f
#define INV_TEMP 10.0f   // 1/TEMP, TEMP=0.1

// scratch (zero-initialized __device__ globals)
__device__ float4       g_scal[2 * TT];   // per-CTA {den, dot, na2, nb2}
__device__ unsigned int g_cnt[TT];        // per-t pair counters
__device__ float        g_partial[TT];    // per-t losses
__device__ unsigned int g_cnt2;           // global finish counter

// asm-forced vector load: batches are truly back-to-back in SASS.
__device__ __forceinline__ float4 ldg128(const float4* p) {
    float4 v;
    asm volatile("ld.global.nc.v4.f32 {%0,%1,%2,%3}, [%4];"
                 : "=f"(v.x), "=f"(v.y), "=f"(v.z), "=f"(v.w)
                 : "l"(p));
    return v;
}

#define ACC(v)                                          \
    s0 += (v).x; s1 += (v).y; s2 += (v).z; s3 += (v).w; \
    q0 = fmaf((v).x, (v).x, q0); q1 = fmaf((v).y, (v).y, q1); \
    q2 = fmaf((v).z, (v).z, q2); q3 = fmaf((v).w, (v).w, q3)

// Two CTAs per t, split over E (512 features each). 128 threads; thread tid
// owns float4 column g*128+tid. All 128 negatives, asm MLP=8.
// Pair combine = 4 scalars; pair-last CTA finishes the loss.
__global__ __launch_bounds__(128, 8) void contloss_esplit(
    const int*   __restrict__ index,
    const float* __restrict__ z1,
    const float* __restrict__ z2,
    const int*   __restrict__ neg_s,
    const int*   __restrict__ neg_w,
    float*       __restrict__ out)
{
    const int blk = blockIdx.x;
    const int t   = blk >> 1;
    const int g   = blk & 1;
    const int tid = threadIdx.x;

    // row offset (float4 units) + this CTA's half-row base
    __shared__ int sh_off[NNEG];
    {
        const int j = t * NNEG + tid;
        sh_off[tid] = (neg_s[j] * BZ + neg_w[j]) * (EE / 4) + g * 128;
    }
    __syncthreads();

    const float4* __restrict__ z1v = (const float4*)z1;

    float s0 = 0.f, s1 = 0.f, s2 = 0.f, s3 = 0.f;
    float q0 = 0.f, q1 = 0.f, q2 = 0.f, q3 = 0.f;

    for (int n = 0; n < NNEG; n += 8) {
        const float4 v0 = ldg128(z1v + sh_off[n + 0] + tid);
        const float4 v1 = ldg128(z1v + sh_off[n + 1] + tid);
        const float4 v2 = ldg128(z1v + sh_off[n + 2] + tid);
        const float4 v3 = ldg128(z1v + sh_off[n + 3] + tid);
        const float4 v4 = ldg128(z1v + sh_off[n + 4] + tid);
        const float4 v5 = ldg128(z1v + sh_off[n + 5] + tid);
        const float4 v6 = ldg128(z1v + sh_off[n + 6] + tid);
        const float4 v7 = ldg128(z1v + sh_off[n + 7] + tid);

        ACC(v0); ACC(v1); ACC(v2); ACC(v3);
        ACC(v4); ACC(v5); ACC(v6); ACC(v7);
    }

    // anchor (orig) and positive (adv), this CTA's half-row
    const int bidx  = __ldg(index + t);
    const int arow4 = (t * BZ + bidx) * (EE / 4) + g * 128;
    const float4 vo = __ldg(z1v + arow4 + tid);
    const float4 va = __ldg((const float4*)z2 + arow4 + tid);

    const float sqrtN = sqrtf((float)NNEG);

    float den = 0.f;
    {
        float o, sm, qq;
        o = vo.x; sm = s0; qq = q0;
        den += expf((o * sm) / (fmaxf(sqrtf(qq), EPSV) * fmaxf(sqrtN * fabsf(o), EPSV)) * INV_TEMP);
        o = vo.y; sm = s1; qq = q1;
        den += expf((o * sm) / (fmaxf(sqrtf(qq), EPSV) * fmaxf(sqrtN * fabsf(o), EPSV)) * INV_TEMP);
        o = vo.z; sm = s2; qq = q2;
        den += expf((o * sm) / (fmaxf(sqrtf(qq), EPSV) * fmaxf(sqrtN * fabsf(o), EPSV)) * INV_TEMP);
        o = vo.w; sm = s3; qq = q3;
        den += expf((o * sm) / (fmaxf(sqrtf(qq), EPSV) * fmaxf(sqrtN * fabsf(o), EPSV)) * INV_TEMP);
    }
    float dotp = vo.x * va.x + vo.y * va.y + vo.z * va.z + vo.w * va.w;
    float na2  = vo.x * vo.x + vo.y * vo.y + vo.z * vo.z + vo.w * vo.w;
    float nb2  = va.x * va.x + va.y * va.y + va.z * va.z + va.w * va.w;

    // deterministic block reduction over 128 threads (4 warps)
    const int lane = tid & 31;
    const int warp = tid >> 5;
    #pragma unroll
    for (int off = 16; off > 0; off >>= 1) {
        den  += __shfl_down_sync(0xffffffffu, den,  off);
        dotp += __shfl_down_sync(0xffffffffu, dotp, off);
        na2  += __shfl_down_sync(0xffffffffu, na2,  off);
        nb2  += __shfl_down_sync(0xffffffffu, nb2,  off);
    }
    __shared__ float r_den[4], r_dot[4], r_na[4], r_nb[4];
    __shared__ unsigned int sh_rank;
    __shared__ bool sh_last;
    if (lane == 0) {
        r_den[warp] = den; r_dot[warp] = dotp; r_na[warp] = na2; r_nb[warp] = nb2;
    }
    __syncthreads();
    if (tid == 0) {
        float D = 0.f, P = 0.f, A = 0.f, Bv = 0.f;
        #pragma unroll
        for (int w = 0; w < 4; ++w) { D += r_den[w]; P += r_dot[w]; A += r_na[w]; Bv += r_nb[w]; }
        g_scal[blk] = make_float4(D, P, A, Bv);
        __threadfence();
        sh_rank = atomicAdd(&g_cnt[t], 1u);
    }
    __syncthreads();
    if (sh_rank == 0) return;   // first of the pair is done

    // pair-last CTA: combine 4 scalars and finish this t's loss
    if (tid == 0) {
        const float4 mine = g_scal[blk];
        const float4 sibl = g_scal[blk ^ 1];
        const float D  = mine.x + sibl.x;
        const float P  = mine.y + sibl.y;
        const float A  = mine.z + sibl.z;
        const float Bv = mine.w + sibl.w;
        const float pos_cos = P / (fmaxf(sqrtf(A), EPSV) * fmaxf(sqrtf(Bv), EPSV));
        g_partial[t] = logf(D) - pos_cos * INV_TEMP;
        g_cnt[t] = 0u;   // reset for next graph replay
        __threadfence();
        const unsigned int done = atomicAdd(&g_cnt2, 1u);
        sh_last = (done == (unsigned int)(TT - 1));
    }
    __syncthreads();

    // global-last CTA: deterministic tree over the 512 per-t losses
    if (sh_last) {
        __shared__ float sh[128];
        sh[tid] = (g_partial[tid]       + g_partial[tid + 128]) +
                  (g_partial[tid + 256] + g_partial[tid + 384]);
        __syncthreads();
        #pragma unroll
        for (int s = 64; s > 0; s >>= 1) {
            if (tid < s) sh[tid] += sh[tid + s];
            __syncthreads();
        }
        if (tid == 0) {
            out[0] = sh[0];
            g_cnt2 = 0u;   // reset for next graph replay
        }
    }
}

extern "C" void kernel_launch(void* const* d_in, const int* in_sizes, int n_in,
                              void* d_out, int out_size)
{
    const int*   index = (const int*)  d_in[0];
    const float* z1    = (const float*)d_in[1];
    const float* z2    = (const float*)d_in[2];
    const int*   ns    = (const int*)  d_in[3];
    const int*   nw    = (const int*)  d_in[4];

    contloss_esplit<<<2 * TT, 128>>>(index, z1, z2, ns, nw, (float*)d_out);
}

// round 12
// speedup vs baseline: 1.2934x; 1.0022x over previous
#include <cuda_runtime.h>
#include <math.h>

// ContLoss: T=512, B=64, E=1024, N=128
#define TT     512
#define BZ     64
#define EE     1024
#define NNEG   128
#define EPSV   1e-8f
#define INV_TEMP 10.0f   // 1/TEMP, TEMP=0.1

// scratch (zero-initialized __device__ globals)
__device__ float4       g_scal[2 * TT];   // per-CTA {den, dot, na2, nb2}
__device__ unsigned int g_cnt[TT];        // per-t pair counters
__device__ float        g_partial[TT];    // per-t losses
__device__ unsigned int g_cnt2;           // global finish counter

// asm-forced vector load: batches are truly back-to-back in SASS.
__device__ __forceinline__ float4 ldg128(const float4* p) {
    float4 v;
    asm volatile("ld.global.nc.v4.f32 {%0,%1,%2,%3}, [%4];"
                 : "=f"(v.x), "=f"(v.y), "=f"(v.z), "=f"(v.w)
                 : "l"(p));
    return v;
}

#define ACC(v)                                          \
    s0 += (v).x; s1 += (v).y; s2 += (v).z; s3 += (v).w; \
    q0 = fmaf((v).x, (v).x, q0); q1 = fmaf((v).y, (v).y, q1); \
    q2 = fmaf((v).z, (v).z, q2); q3 = fmaf((v).w, (v).w, q3)

// Two CTAs per t, split over E (512 features each). 128 threads; thread tid
// owns float4 column g*128+tid. All 128 negatives, asm MLP=12 (tail MLP=8).
// Pair combine = 4 scalars through scratch; pair-last CTA finishes the loss.
__global__ __launch_bounds__(128, 8) void contloss_esplit(
    const int*   __restrict__ index,
    const float* __restrict__ z1,
    const float* __restrict__ z2,
    const int*   __restrict__ neg_s,
    const int*   __restrict__ neg_w,
    float*       __restrict__ out)
{
    const int blk = blockIdx.x;
    const int t   = blk >> 1;
    const int g   = blk & 1;
    const int tid = threadIdx.x;

    // row offsets (float4 units) + this CTA's half-row base
    __shared__ int sh_off[NNEG];
    {
        const int j = t * NNEG + tid;
        sh_off[tid] = (neg_s[j] * BZ + neg_w[j]) * (EE / 4) + g * 128;
    }
    __syncthreads();

    const float4* __restrict__ z1v = (const float4*)z1;

    float s0 = 0.f, s1 = 0.f, s2 = 0.f, s3 = 0.f;
    float q0 = 0.f, q1 = 0.f, q2 = 0.f, q3 = 0.f;

    // 10 batches of 12 rows (MLP=12)
    for (int n = 0; n < 120; n += 12) {
        const float4 v0  = ldg128(z1v + sh_off[n +  0] + tid);
        const float4 v1  = ldg128(z1v + sh_off[n +  1] + tid);
        const float4 v2  = ldg128(z1v + sh_off[n +  2] + tid);
        const float4 v3  = ldg128(z1v + sh_off[n +  3] + tid);
        const float4 v4  = ldg128(z1v + sh_off[n +  4] + tid);
        const float4 v5  = ldg128(z1v + sh_off[n +  5] + tid);
        const float4 v6  = ldg128(z1v + sh_off[n +  6] + tid);
        const float4 v7  = ldg128(z1v + sh_off[n +  7] + tid);
        const float4 v8  = ldg128(z1v + sh_off[n +  8] + tid);
        const float4 v9  = ldg128(z1v + sh_off[n +  9] + tid);
        const float4 v10 = ldg128(z1v + sh_off[n + 10] + tid);
        const float4 v11 = ldg128(z1v + sh_off[n + 11] + tid);

        ACC(v0); ACC(v1); ACC(v2);  ACC(v3);
        ACC(v4); ACC(v5); ACC(v6);  ACC(v7);
        ACC(v8); ACC(v9); ACC(v10); ACC(v11);
    }
    // tail batch of 8 rows (120..127)
    {
        const float4 v0 = ldg128(z1v + sh_off[120] + tid);
        const float4 v1 = ldg128(z1v + sh_off[121] + tid);
        const float4 v2 = ldg128(z1v + sh_off[122] + tid);
        const float4 v3 = ldg128(z1v + sh_off[123] + tid);
        const float4 v4 = ldg128(z1v + sh_off[124] + tid);
        const float4 v5 = ldg128(z1v + sh_off[125] + tid);
        const float4 v6 = ldg128(z1v + sh_off[126] + tid);
        const float4 v7 = ldg128(z1v + sh_off[127] + tid);

        ACC(v0); ACC(v1); ACC(v2); ACC(v3);
        ACC(v4); ACC(v5); ACC(v6); ACC(v7);
    }

    // anchor (orig) and positive (adv), this CTA's half-row
    const int bidx  = __ldg(index + t);
    const int arow4 = (t * BZ + bidx) * (EE / 4) + g * 128;
    const float4 vo = __ldg(z1v + arow4 + tid);
    const float4 va = __ldg((const float4*)z2 + arow4 + tid);

    const float sqrtN = sqrtf((float)NNEG);

    float den = 0.f;
    {
        float o, sm, qq;
        o = vo.x; sm = s0; qq = q0;
        den += expf((o * sm) / (fmaxf(sqrtf(qq), EPSV) * fmaxf(sqrtN * fabsf(o), EPSV)) * INV_TEMP);
        o = vo.y; sm = s1; qq = q1;
        den += expf((o * sm) / (fmaxf(sqrtf(qq), EPSV) * fmaxf(sqrtN * fabsf(o), EPSV)) * INV_TEMP);
        o = vo.z; sm = s2; qq = q2;
        den += expf((o * sm) / (fmaxf(sqrtf(qq), EPSV) * fmaxf(sqrtN * fabsf(o), EPSV)) * INV_TEMP);
        o = vo.w; sm = s3; qq = q3;
        den += expf((o * sm) / (fmaxf(sqrtf(qq), EPSV) * fmaxf(sqrtN * fabsf(o), EPSV)) * INV_TEMP);
    }
    float dotp = vo.x * va.x + vo.y * va.y + vo.z * va.z + vo.w * va.w;
    float na2  = vo.x * vo.x + vo.y * vo.y + vo.z * vo.z + vo.w * vo.w;
    float nb2  = va.x * va.x + va.y * va.y + va.z * va.z + va.w * va.w;

    // deterministic block reduction over 128 threads (4 warps)
    const int lane = tid & 31;
    const int warp = tid >> 5;
    #pragma unroll
    for (int off = 16; off > 0; off >>= 1) {
        den  += __shfl_down_sync(0xffffffffu, den,  off);
        dotp += __shfl_down_sync(0xffffffffu, dotp, off);
        na2  += __shfl_down_sync(0xffffffffu, na2,  off);
        nb2  += __shfl_down_sync(0xffffffffu, nb2,  off);
    }
    __shared__ float r_den[4], r_dot[4], r_na[4], r_nb[4];
    __shared__ unsigned int sh_rank;
    __shared__ bool sh_last;
    if (lane == 0) {
        r_den[warp] = den; r_dot[warp] = dotp; r_na[warp] = na2; r_nb[warp] = nb2;
    }
    __syncthreads();
    if (tid == 0) {
        float D = 0.f, P = 0.f, A = 0.f, Bv = 0.f;
        #pragma unroll
        for (int w = 0; w < 4; ++w) { D += r_den[w]; P += r_dot[w]; A += r_na[w]; Bv += r_nb[w]; }
        g_scal[blk] = make_float4(D, P, A, Bv);
        __threadfence();
        sh_rank = atomicAdd(&g_cnt[t], 1u);
    }
    __syncthreads();
    if (sh_rank == 0) return;   // first of the pair is done

    // pair-last CTA: combine 4 scalars and finish this t's loss
    if (tid == 0) {
        const float4 mine = g_scal[blk];
        const float4 sibl = g_scal[blk ^ 1];
        const float D  = mine.x + sibl.x;
        const float P  = mine.y + sibl.y;
        const float A  = mine.z + sibl.z;
        const float Bv = mine.w + sibl.w;
        const float pos_cos = P / (fmaxf(sqrtf(A), EPSV) * fmaxf(sqrtf(Bv), EPSV));
        g_partial[t] = logf(D) - pos_cos * INV_TEMP;
        g_cnt[t] = 0u;   // reset for next graph replay
        __threadfence();
        const unsigned int done = atomicAdd(&g_cnt2, 1u);
        sh_last = (done == (unsigned int)(TT - 1));
    }
    __syncthreads();

    // global-last CTA: deterministic tree over the 512 per-t losses
    if (sh_last) {
        __shared__ float sh[128];
        sh[tid] = (g_partial[tid]       + g_partial[tid + 128]) +
                  (g_partial[tid + 256] + g_partial[tid + 384]);
        __syncthreads();
        #pragma unroll
        for (int s = 64; s > 0; s >>= 1) {
            if (tid < s) sh[tid] += sh[tid + s];
            __syncthreads();
        }
        if (tid == 0) {
            out[0] = sh[0];
            g_cnt2 = 0u;   // reset for next graph replay
        }
    }
}

extern "C" void kernel_launch(void* const* d_in, const int* in_sizes, int n_in,
                              void* d_out, int out_size)
{
    const int*   index = (const int*)  d_in[0];
    const float* z1    = (const float*)d_in[1];
    const float* z2    = (const float*)d_in[2];
    const int*   ns    = (const int*)  d_in[3];
    const int*   nw    = (const int*)  d_in[4];

    contloss_esplit<<<2 * TT, 128>>>(index, z1, z2, ns, nw, (float*)d_out);
}

// round 13
// speedup vs baseline: 1.3477x; 1.0420x over previous
#include <cuda_runtime.h>
#include <math.h>

// ContLoss: T=512, B=64, E=1024, N=128
#define TT     512
#define BZ     64
#define EE     1024
#define NNEG   128
#define EPSV   1e-8f
#define INV_TEMP 10.0f   // 1/TEMP, TEMP=0.1

#define FULLT  444              // t's handled by full CTAs (3 per SM exactly)
#define NPAIR  (TT - FULLT)     // 68 t's handled by E-split CTA pairs

// scratch (zero-initialized __device__ globals)
__device__ float4       g_scal[2 * NPAIR];  // per-half-CTA {den, dot, na2, nb2}
__device__ unsigned int g_cnt[NPAIR];       // per-pair counters
__device__ float        g_partial[TT];      // per-t losses
__device__ unsigned int g_done;             // t-completion counter

// asm-forced loads: batches are truly back-to-back in SASS (no sinking).
__device__ __forceinline__ float4 ldg128(const float4* p) {
    float4 v;
    asm volatile("ld.global.nc.v4.f32 {%0,%1,%2,%3}, [%4];"
                 : "=f"(v.x), "=f"(v.y), "=f"(v.z), "=f"(v.w)
                 : "l"(p));
    return v;
}
__device__ __forceinline__ float2 ldg64(const float2* p) {
    float2 v;
    asm volatile("ld.global.nc.v2.f32 {%0,%1}, [%2];"
                 : "=f"(v.x), "=f"(v.y) : "l"(p));
    return v;
}

#define ACC4(v)                                         \
    s0 += (v).x; s1 += (v).y; s2 += (v).z; s3 += (v).w; \
    q0 = fmaf((v).x, (v).x, q0); q1 = fmaf((v).y, (v).y, q1); \
    q2 = fmaf((v).z, (v).z, q2); q3 = fmaf((v).w, (v).w, q3)

#define ACC2(v)                     \
    s0 += (v).x; s1 += (v).y;       \
    q0 = fmaf((v).x, (v).x, q0); q1 = fmaf((v).y, (v).y, q1)

__global__ __launch_bounds__(256, 4) void contloss_mixed(
    const int*   __restrict__ index,
    const float* __restrict__ z1,
    const float* __restrict__ z2,
    const int*   __restrict__ neg_s,
    const int*   __restrict__ neg_w,
    float*       __restrict__ out)
{
    const int blk = blockIdx.x;
    const int tid = threadIdx.x;

    __shared__ int   sh_off[NNEG];
    __shared__ float r_den[8], r_dot[8], r_na[8], r_nb[8];
    __shared__ bool  sh_last;
    __shared__ unsigned int sh_rank;

    const int lane = tid & 31;
    const int warp = tid >> 5;
    const float sqrtN = sqrtf((float)NNEG);

    bool  contribute = false;   // does this CTA write a g_partial[t]?
    int   my_t = 0;
    float my_loss = 0.f;

    if (blk < FULLT) {
        // ───────── full-t path (identical to R8): t = blk, 256 thr × float4 ─────────
        const int t = blk;
        if (tid < NNEG) {
            const int j = t * NNEG + tid;
            sh_off[tid] = (neg_s[j] * BZ + neg_w[j]) * (EE / 4);
        }
        __syncthreads();

        const float4* __restrict__ z1v = (const float4*)z1;

        float s0 = 0.f, s1 = 0.f, s2 = 0.f, s3 = 0.f;
        float q0 = 0.f, q1 = 0.f, q2 = 0.f, q3 = 0.f;

        for (int n = 0; n < NNEG; n += 8) {
            const float4 v0 = ldg128(z1v + sh_off[n + 0] + tid);
            const float4 v1 = ldg128(z1v + sh_off[n + 1] + tid);
            const float4 v2 = ldg128(z1v + sh_off[n + 2] + tid);
            const float4 v3 = ldg128(z1v + sh_off[n + 3] + tid);
            const float4 v4 = ldg128(z1v + sh_off[n + 4] + tid);
            const float4 v5 = ldg128(z1v + sh_off[n + 5] + tid);
            const float4 v6 = ldg128(z1v + sh_off[n + 6] + tid);
            const float4 v7 = ldg128(z1v + sh_off[n + 7] + tid);
            ACC4(v0); ACC4(v1); ACC4(v2); ACC4(v3);
            ACC4(v4); ACC4(v5); ACC4(v6); ACC4(v7);
        }

        const int bidx  = __ldg(index + t);
        const int arow4 = (t * BZ + bidx) * (EE / 4);
        const float4 vo = __ldg(z1v + arow4 + tid);
        const float4 va = __ldg((const float4*)z2 + arow4 + tid);

        float den = 0.f;
        {
            float o, sm, qq;
            o = vo.x; sm = s0; qq = q0;
            den += expf((o * sm) / (fmaxf(sqrtf(qq), EPSV) * fmaxf(sqrtN * fabsf(o), EPSV)) * INV_TEMP);
            o = vo.y; sm = s1; qq = q1;
            den += expf((o * sm) / (fmaxf(sqrtf(qq), EPSV) * fmaxf(sqrtN * fabsf(o), EPSV)) * INV_TEMP);
            o = vo.z; sm = s2; qq = q2;
            den += expf((o * sm) / (fmaxf(sqrtf(qq), EPSV) * fmaxf(sqrtN * fabsf(o), EPSV)) * INV_TEMP);
            o = vo.w; sm = s3; qq = q3;
            den += expf((o * sm) / (fmaxf(sqrtf(qq), EPSV) * fmaxf(sqrtN * fabsf(o), EPSV)) * INV_TEMP);
        }
        float dotp = vo.x * va.x + vo.y * va.y + vo.z * va.z + vo.w * va.w;
        float na2  = vo.x * vo.x + vo.y * vo.y + vo.z * vo.z + vo.w * vo.w;
        float nb2  = va.x * va.x + va.y * va.y + va.z * va.z + va.w * va.w;

        #pragma unroll
        for (int off = 16; off > 0; off >>= 1) {
            den  += __shfl_down_sync(0xffffffffu, den,  off);
            dotp += __shfl_down_sync(0xffffffffu, dotp, off);
            na2  += __shfl_down_sync(0xffffffffu, na2,  off);
            nb2  += __shfl_down_sync(0xffffffffu, nb2,  off);
        }
        if (lane == 0) { r_den[warp] = den; r_dot[warp] = dotp; r_na[warp] = na2; r_nb[warp] = nb2; }
        __syncthreads();
        if (tid == 0) {
            float D = 0.f, P = 0.f, A = 0.f, Bv = 0.f;
            #pragma unroll
            for (int w = 0; w < 8; ++w) { D += r_den[w]; P += r_dot[w]; A += r_na[w]; Bv += r_nb[w]; }
            const float pos_cos = P / (fmaxf(sqrtf(A), EPSV) * fmaxf(sqrtf(Bv), EPSV));
            my_loss = logf(D) - pos_cos * INV_TEMP;
        }
        contribute = true;
        my_t = t;
    } else {
        // ───────── half path: E-split pair, t = FULLT + idx/2, 256 thr × float2 ─────────
        const int idx = blk - FULLT;
        const int t   = FULLT + (idx >> 1);
        const int g   = idx & 1;

        if (tid < NNEG) {
            const int j = t * NNEG + tid;
            // offsets in float2 units, biased to this CTA's E-half
            sh_off[tid] = (neg_s[j] * BZ + neg_w[j]) * (EE / 2) + g * 256;
        }
        __syncthreads();

        const float2* __restrict__ z1f = (const float2*)z1;

        float s0 = 0.f, s1 = 0.f, q0 = 0.f, q1 = 0.f;

        for (int n = 0; n < NNEG; n += 8) {
            const float2 v0 = ldg64(z1f + sh_off[n + 0] + tid);
            const float2 v1 = ldg64(z1f + sh_off[n + 1] + tid);
            const float2 v2 = ldg64(z1f + sh_off[n + 2] + tid);
            const float2 v3 = ldg64(z1f + sh_off[n + 3] + tid);
            const float2 v4 = ldg64(z1f + sh_off[n + 4] + tid);
            const float2 v5 = ldg64(z1f + sh_off[n + 5] + tid);
            const float2 v6 = ldg64(z1f + sh_off[n + 6] + tid);
            const float2 v7 = ldg64(z1f + sh_off[n + 7] + tid);
            ACC2(v0); ACC2(v1); ACC2(v2); ACC2(v3);
            ACC2(v4); ACC2(v5); ACC2(v6); ACC2(v7);
        }

        const int bidx  = __ldg(index + t);
        const int arow2 = (t * BZ + bidx) * (EE / 2) + g * 256;
        const float2 vo = __ldg(z1f + arow2 + tid);
        const float2 va = __ldg((const float2*)z2 + arow2 + tid);

        float den = 0.f;
        {
            float o, sm, qq;
            o = vo.x; sm = s0; qq = q0;
            den += expf((o * sm) / (fmaxf(sqrtf(qq), EPSV) * fmaxf(sqrtN * fabsf(o), EPSV)) * INV_TEMP);
            o = vo.y; sm = s1; qq = q1;
            den += expf((o * sm) / (fmaxf(sqrtf(qq), EPSV) * fmaxf(sqrtN * fabsf(o), EPSV)) * INV_TEMP);
        }
        float dotp = vo.x * va.x + vo.y * va.y;
        float na2  = vo.x * vo.x + vo.y * vo.y;
        float nb2  = va.x * va.x + va.y * va.y;

        #pragma unroll
        for (int off = 16; off > 0; off >>= 1) {
            den  += __shfl_down_sync(0xffffffffu, den,  off);
            dotp += __shfl_down_sync(0xffffffffu, dotp, off);
            na2  += __shfl_down_sync(0xffffffffu, na2,  off);
            nb2  += __shfl_down_sync(0xffffffffu, nb2,  off);
        }
        if (lane == 0) { r_den[warp] = den; r_dot[warp] = dotp; r_na[warp] = na2; r_nb[warp] = nb2; }
        __syncthreads();
        if (tid == 0) {
            float D = 0.f, P = 0.f, A = 0.f, Bv = 0.f;
            #pragma unroll
            for (int w = 0; w < 8; ++w) { D += r_den[w]; P += r_dot[w]; A += r_na[w]; Bv += r_nb[w]; }
            g_scal[idx] = make_float4(D, P, A, Bv);
            __threadfence();
            sh_rank = atomicAdd(&g_cnt[idx >> 1], 1u);
        }
        __syncthreads();
        if (sh_rank == 0) return;   // first of the pair exits

        if (tid == 0) {
            const float4 mine = g_scal[idx];
            const float4 sibl = g_scal[idx ^ 1];
            const float D  = mine.x + sibl.x;
            const float P  = mine.y + sibl.y;
            const float A  = mine.z + sibl.z;
            const float Bv = mine.w + sibl.w;
            const float pos_cos = P / (fmaxf(sqrtf(A), EPSV) * fmaxf(sqrtf(Bv), EPSV));
            my_loss = logf(D) - pos_cos * INV_TEMP;
            g_cnt[idx >> 1] = 0u;   // reset for next replay
        }
        contribute = true;
        my_t = t;
    }

    // ───────── publish this t's loss; last finisher reduces all 512 ─────────
    if (contribute) {
        if (tid == 0) {
            g_partial[my_t] = my_loss;
            __threadfence();
            const unsigned int done = atomicAdd(&g_done, 1u);
            sh_last = (done == (unsigned int)(TT - 1));
        }
        __syncthreads();

        if (sh_last) {
            __shared__ float sh[256];
            sh[tid] = g_partial[tid] + g_partial[tid + 256];
            __syncthreads();
            #pragma unroll
            for (int s = 128; s > 0; s >>= 1) {
                if (tid < s) sh[tid] += sh[tid + s];
                __syncthreads();
            }
            if (tid == 0) {
                out[0] = sh[0];
                g_done = 0u;   // reset for next graph replay
            }
        }
    }
}

extern "C" void kernel_launch(void* const* d_in, const int* in_sizes, int n_in,
                              void* d_out, int out_size)
{
    const int*   index = (const int*)  d_in[0];
    const float* z1    = (const float*)d_in[1];
    const float* z2    = (const float*)d_in[2];
    const int*   ns    = (const int*)  d_in[3];
    const int*   nw    = (const int*)  d_in[4];

    contloss_mixed<<<FULLT + 2 * NPAIR, 256>>>(index, z1, z2, ns, nw, (float*)d_out);
}

// round 15
// speedup vs baseline: 1.3509x; 1.0023x over previous
#include <cuda_runtime.h>
#include <math.h>

// ContLoss: T=512, B=64, E=1024, N=128
#define TT     512
#define BZ     64
#define EE     1024
#define NNEG   128
#define EPSV   1e-8f
#define INV_TEMP 10.0f   // 1/TEMP, TEMP=0.1

// scratch (zero-initialized __device__ globals)
__device__ float        g_partial[TT];
__device__ unsigned int g_count;

// evict-last policy via createpolicy + cache_hint (the only form ptxas
// accepts for 16B loads on sm_103). asm volatile ordering keeps batches
// back-to-back in SASS (true MLP=8).
__device__ __forceinline__ unsigned long long mk_policy_el() {
    unsigned long long pol;
    asm volatile("createpolicy.fractional.L2::evict_last.b64 %0, 1.0;" : "=l"(pol));
    return pol;
}
__device__ __forceinline__ float4 ldg128_el(const float4* p, unsigned long long pol) {
    float4 v;
    asm volatile("ld.global.nc.L2::cache_hint.v4.f32 {%0,%1,%2,%3}, [%4], %5;"
                 : "=f"(v.x), "=f"(v.y), "=f"(v.z), "=f"(v.w)
                 : "l"(p), "l"(pol));
    return v;
}

#define ACC(v)                                          \
    s0 += (v).x; s1 += (v).y; s2 += (v).z; s3 += (v).w; \
    q0 = fmaf((v).x, (v).x, q0); q1 = fmaf((v).y, (v).y, q1); \
    q2 = fmaf((v).z, (v).z, q2); q3 = fmaf((v).w, (v).w, q3)

// One CTA per t. 256 threads; thread tid owns float4 column tid. MLP=8.
__global__ __launch_bounds__(256, 4) void contloss_fused(
    const int*   __restrict__ index,
    const float* __restrict__ z1,
    const float* __restrict__ z2,
    const int*   __restrict__ neg_s,
    const int*   __restrict__ neg_w,
    float*       __restrict__ out)
{
    const int t   = blockIdx.x;
    const int tid = threadIdx.x;

    __shared__ int sh_off[NNEG];
    if (tid < NNEG) {
        const int j = t * NNEG + tid;
        sh_off[tid] = (neg_s[j] * BZ + neg_w[j]) * (EE / 4);
    }
    __syncthreads();

    const float4* __restrict__ z1v = (const float4*)z1;
    const unsigned long long pol = mk_policy_el();

    float s0 = 0.f, s1 = 0.f, s2 = 0.f, s3 = 0.f;
    float q0 = 0.f, q1 = 0.f, q2 = 0.f, q3 = 0.f;

    for (int n = 0; n < NNEG; n += 8) {
        const float4 v0 = ldg128_el(z1v + sh_off[n + 0] + tid, pol);
        const float4 v1 = ldg128_el(z1v + sh_off[n + 1] + tid, pol);
        const float4 v2 = ldg128_el(z1v + sh_off[n + 2] + tid, pol);
        const float4 v3 = ldg128_el(z1v + sh_off[n + 3] + tid, pol);
        const float4 v4 = ldg128_el(z1v + sh_off[n + 4] + tid, pol);
        const float4 v5 = ldg128_el(z1v + sh_off[n + 5] + tid, pol);
        const float4 v6 = ldg128_el(z1v + sh_off[n + 6] + tid, pol);
        const float4 v7 = ldg128_el(z1v + sh_off[n + 7] + tid, pol);

        ACC(v0); ACC(v1); ACC(v2); ACC(v3);
        ACC(v4); ACC(v5); ACC(v6); ACC(v7);
    }

    // anchor (orig) and positive (adv) rows
    const int bidx  = __ldg(index + t);
    const int arow4 = (t * BZ + bidx) * (EE / 4);
    const float4 vo = __ldg(z1v + arow4 + tid);
    const float4 va = __ldg((const float4*)z2 + arow4 + tid);

    const float sqrtN = sqrtf((float)NNEG);

    float den = 0.f;
    {
        float o, sm, qq;
        o = vo.x; sm = s0; qq = q0;
        den += expf((o * sm) / (fmaxf(sqrtf(qq), EPSV) * fmaxf(sqrtN * fabsf(o), EPSV)) * INV_TEMP);
        o = vo.y; sm = s1; qq = q1;
        den += expf((o * sm) / (fmaxf(sqrtf(qq), EPSV) * fmaxf(sqrtN * fabsf(o), EPSV)) * INV_TEMP);
        o = vo.z; sm = s2; qq = q2;
        den += expf((o * sm) / (fmaxf(sqrtf(qq), EPSV) * fmaxf(sqrtN * fabsf(o), EPSV)) * INV_TEMP);
        o = vo.w; sm = s3; qq = q3;
        den += expf((o * sm) / (fmaxf(sqrtf(qq), EPSV) * fmaxf(sqrtN * fabsf(o), EPSV)) * INV_TEMP);
    }
    float dotp = vo.x * va.x + vo.y * va.y + vo.z * va.z + vo.w * va.w;
    float na2  = vo.x * vo.x + vo.y * vo.y + vo.z * vo.z + vo.w * vo.w;
    float nb2  = va.x * va.x + va.y * va.y + va.z * va.z + va.w * va.w;

    // deterministic block reduction
    const int lane = tid & 31;
    const int warp = tid >> 5;
    #pragma unroll
    for (int off = 16; off > 0; off >>= 1) {
        den  += __shfl_down_sync(0xffffffffu, den,  off);
        dotp += __shfl_down_sync(0xffffffffu, dotp, off);
        na2  += __shfl_down_sync(0xffffffffu, na2,  off);
        nb2  += __shfl_down_sync(0xffffffffu, nb2,  off);
    }
    __shared__ float r_den[8], r_dot[8], r_na[8], r_nb[8];
    __shared__ bool  sh_last;
    if (lane == 0) {
        r_den[warp] = den; r_dot[warp] = dotp; r_na[warp] = na2; r_nb[warp] = nb2;
    }
    __syncthreads();
    if (tid == 0) {
        float D = 0.f, P = 0.f, A = 0.f, Bv = 0.f;
        #pragma unroll
        for (int w = 0; w < 8; ++w) { D += r_den[w]; P += r_dot[w]; A += r_na[w]; Bv += r_nb[w]; }
        const float pos_cos = P / (fmaxf(sqrtf(A), EPSV) * fmaxf(sqrtf(Bv), EPSV));
        g_partial[t] = logf(D) - pos_cos * INV_TEMP;
        __threadfence();
        const unsigned int done = atomicAdd(&g_count, 1u);
        sh_last = (done == (unsigned int)(gridDim.x - 1));
    }
    __syncthreads();

    // global-last CTA: deterministic tree over the 512 per-t losses
    if (sh_last) {
        __shared__ float sh[256];
        sh[tid] = g_partial[tid] + g_partial[tid + 256];
        __syncthreads();
        #pragma unroll
        for (int s = 128; s > 0; s >>= 1) {
            if (tid < s) sh[tid] += sh[tid + s];
            __syncthreads();
        }
        if (tid == 0) {
            out[0]  = sh[0];
            g_count = 0u;   // reset for next graph replay
        }
    }
}

extern "C" void kernel_launch(void* const* d_in, const int* in_sizes, int n_in,
                              void* d_out, int out_size)
{
    const int*   index = (const int*)  d_in[0];
    const float* z1    = (const float*)d_in[1];
    const float* z2    = (const float*)d_in[2];
    const int*   ns    = (const int*)  d_in[3];
    const int*   nw    = (const int*)  d_in[4];

    contloss_fused<<<TT, 256>>>(index, z1, z2, ns, nw, (float*)d_out);
}